// round 12
// baseline (speedup 1.0000x reference)
#include <cuda_runtime.h>
#include <cuda_fp16.h>
#include <cstdint>

// Problem constants
#define BB 4
#define NN 4096
#define KK 32
#define CC 64
#define FD 128
#define DHH 128
#define BN (BB * NN)
#define NT2 (BN / 2)           // M=64 tiles: 2 points per tile

// Scratch (no cudaMalloc allowed)
__device__ __half g_ctr_h[(size_t)BN * FD];   // h(ctr*s + b)
__device__ __half g_nbr_h[(size_t)BN * FD];   // h(v*s)
__device__ float  g_pooled[(size_t)BN * DHH];

// ---------------------------------------------------------------------------
// PTX helpers — baseline sm_80+ instructions only (compute_103-safe).
// ---------------------------------------------------------------------------
__device__ __forceinline__ uint32_t smem_u32(const void* p) {
    uint32_t a;
    asm("{ .reg .u64 t; cvta.to.shared.u64 t, %1; cvt.u32.u64 %0, t; }"
        : "=r"(a) : "l"(p));
    return a;
}

#define LDSM_X4(r0, r1, r2, r3, addr)                                        \
    asm volatile("ldmatrix.sync.aligned.m8n8.x4.shared.b16 {%0,%1,%2,%3}, [%4];" \
                 : "=r"(r0), "=r"(r1), "=r"(r2), "=r"(r3) : "r"(addr))

#define MMA_F16_F32(d, a, b0, b1)                                            \
    asm volatile("mma.sync.aligned.m16n8k16.row.col.f32.f16.f16.f32 "        \
                 "{%0,%1,%2,%3}, {%4,%5,%6,%7}, {%8,%9}, {%0,%1,%2,%3};"     \
                 : "+f"((d)[0]), "+f"((d)[1]), "+f"((d)[2]), "+f"((d)[3])    \
                 : "r"((a)[0]), "r"((a)[1]), "r"((a)[2]), "r"((a)[3]),       \
                   "r"(b0), "r"(b1))

__device__ __forceinline__ uint32_t h2u(__half2 h) { return *(uint32_t*)&h; }

// ---------------------------------------------------------------------------
// Kernel 1: precompute pre-scaled fp16 tables (512 blocks, 32 pts each).
//   g_ctr_h[p][f] = h( (U1|Gv)[f]*s[f] + b[f] )
//   g_nbr_h[p][f] = h( (U2|Gv)[f]*s[f] )
// Also performs the xyz passthrough copy (replaces separate memcpy).
// ---------------------------------------------------------------------------
#define WGV_S 68
__global__ void __launch_bounds__(256) precompute_kernel(
    const float* __restrict__ xyz, const float* __restrict__ features,
    const float* __restrict__ W_gu, const float* __restrict__ W_gv,
    const float* __restrict__ s_gu, const float* __restrict__ b_gu,
    const float* __restrict__ s_gv, const float* __restrict__ b_gv,
    float* __restrict__ out_xyz)
{
    __shared__ float sWgv[64 * WGV_S];
    __shared__ float sWgu[64 * 6];
    __shared__ float sF[64 * 33];
    __shared__ float sXyz[32 * 3];
    __shared__ float sOut[32 * 132];
    __shared__ float sS[128], sB[128];

    int t = threadIdx.x;
    int p0 = blockIdx.x * 32;
    int b = p0 >> 12;
    int n0 = p0 & (NN - 1);

    // xyz passthrough (independent of the rest)
    if (out_xyz) {
        for (int e = blockIdx.x * 256 + t; e < BB * NN * 3; e += gridDim.x * 256)
            out_xyz[e] = xyz[e];
    }

    for (int e = t; e < 64 * 64; e += 256)
        sWgv[(e & 63) * WGV_S + (e >> 6)] = W_gv[e];
    for (int e = t; e < 64 * 6; e += 256)
        sWgu[e] = W_gu[e];
    for (int e = t; e < 64 * 32; e += 256) {
        int c = e >> 5, np = e & 31;
        sF[c * 33 + np] = features[(size_t)b * CC * NN + (size_t)c * NN + n0 + np];
    }
    for (int e = t; e < 96; e += 256)
        sXyz[e] = xyz[(size_t)p0 * 3 + e];
    if (t < 64) { sS[t] = s_gu[t]; sB[t] = b_gu[t]; }
    else if (t < 128) { sS[t] = s_gv[t - 64]; sB[t] = b_gv[t - 64]; }
    __syncthreads();

    // Gv: thread (np = t&31, o0 = (t>>5)*8)
    {
        int np = t & 31;
        int o0 = (t >> 5) << 3;
        float acc[8];
#pragma unroll
        for (int j = 0; j < 8; j++) acc[j] = 0.f;
#pragma unroll 16
        for (int c = 0; c < 64; c++) {
            float a = sF[c * 33 + np];
            const float4* wp = (const float4*)&sWgv[c * WGV_S + o0];
            float4 w0 = wp[0], w1 = wp[1];
            acc[0] += a * w0.x; acc[1] += a * w0.y;
            acc[2] += a * w0.z; acc[3] += a * w0.w;
            acc[4] += a * w1.x; acc[5] += a * w1.y;
            acc[6] += a * w1.z; acc[7] += a * w1.w;
        }
#pragma unroll
        for (int j = 0; j < 8; j++)
            sOut[np * 132 + 64 + o0 + j] = acc[j];
    }
    // U1 into cols 0..63
    for (int e = t; e < 32 * 64; e += 256) {
        int np = e >> 6, o = e & 63;
        float x0 = sXyz[np * 3], x1 = sXyz[np * 3 + 1], x2 = sXyz[np * 3 + 2];
        sOut[np * 132 + o] = sWgu[o * 6 + 0] * x0 + sWgu[o * 6 + 1] * x1 + sWgu[o * 6 + 2] * x2;
    }
    __syncthreads();
    // write ctr table: scale + bias, fp16
    for (int e = t * 8; e < 32 * 128; e += 2048) {
        int np = e >> 7, f = e & 127;
        const float* src = &sOut[np * 132 + f];
        float4 x0 = *(const float4*)src, x1 = *(const float4*)(src + 4);
        float4 s0 = *(const float4*)&sS[f], s1 = *(const float4*)&sS[f + 4];
        float4 c0 = *(const float4*)&sB[f], c1 = *(const float4*)&sB[f + 4];
        uint4 o;
        o.x = h2u(__float22half2_rn(make_float2(x0.x * s0.x + c0.x, x0.y * s0.y + c0.y)));
        o.y = h2u(__float22half2_rn(make_float2(x0.z * s0.z + c0.z, x0.w * s0.w + c0.w)));
        o.z = h2u(__float22half2_rn(make_float2(x1.x * s1.x + c1.x, x1.y * s1.y + c1.y)));
        o.w = h2u(__float22half2_rn(make_float2(x1.z * s1.z + c1.z, x1.w * s1.w + c1.w)));
        *(uint4*)&g_ctr_h[(size_t)p0 * FD + e] = o;
    }
    __syncthreads();
    // overwrite cols 0..63 with U2
    for (int e = t; e < 32 * 64; e += 256) {
        int np = e >> 6, o = e & 63;
        float x0 = sXyz[np * 3], x1 = sXyz[np * 3 + 1], x2 = sXyz[np * 3 + 2];
        sOut[np * 132 + o] = sWgu[o * 6 + 3] * x0 + sWgu[o * 6 + 4] * x1 + sWgu[o * 6 + 5] * x2;
    }
    __syncthreads();
    // write nbr table: scale only, fp16
    for (int e = t * 8; e < 32 * 128; e += 2048) {
        int np = e >> 7, f = e & 127;
        const float* src = &sOut[np * 132 + f];
        float4 x0 = *(const float4*)src, x1 = *(const float4*)(src + 4);
        float4 s0 = *(const float4*)&sS[f], s1 = *(const float4*)&sS[f + 4];
        uint4 o;
        o.x = h2u(__float22half2_rn(make_float2(x0.x * s0.x, x0.y * s0.y)));
        o.y = h2u(__float22half2_rn(make_float2(x0.z * s0.z, x0.w * s0.w)));
        o.z = h2u(__float22half2_rn(make_float2(x1.x * s1.x, x1.y * s1.y)));
        o.w = h2u(__float22half2_rn(make_float2(x1.z * s1.z, x1.w * s1.w)));
        *(uint4*)&g_nbr_h[(size_t)p0 * FD + e] = o;
    }
}

// ---------------------------------------------------------------------------
// Kernel 2 (main): 256-thread CTAs, M=64 tiles (2 points), 2 CTAs/SM.
// Grid = 296 = 148 SMs x 2 resident CTAs exactly (no straggler tail).
// B fragments hoisted in registers, double-buffered A smem, one barrier/tile.
// ---------------------------------------------------------------------------
#define MAIN_GRID 296
#define RSB 272
#define RSW 68
#define S_WH 0                       // W_h fp16       34816
#define S_A0 34816                   // A buf 0        17408
#define S_A1 52224                   // A buf 1        17408
#define S_IDX 69632                  // 2x64 ints      512
#define S_SH  70144                  // s_h            512
#define S_BH  70656                  // b_h            512
#define MAIN_SMEM 71168

__global__ void __launch_bounds__(256, 2) main_kernel(
    const int* __restrict__ idx,
    const float* __restrict__ W_h,
    const float* __restrict__ s_h, const float* __restrict__ b_h)
{
    extern __shared__ __align__(16) char smem[];
    uint32_t sbase = smem_u32(smem);
    uint32_t* sWh = (uint32_t*)(smem + S_WH);
    int*   s_idx = (int*)(smem + S_IDX);
    float* s_sh = (float*)(smem + S_SH);
    float* s_bh = (float*)(smem + S_BH);

    int t = threadIdx.x;
    int lane = t & 31;
    int w = t >> 5;

    // gather mapping: halves octet fo (8fo..8fo+7), row group rg (4 rows)
    int fo = t & 15;
    int rg = t >> 4;            // 0..15 -> rows rg*4 .. rg*4+3
    int rowb = rg * 4;
    int ptg = rg >> 3;          // point of this row group (0/1)

    if (t < 128) { s_sh[t] = s_h[t]; s_bh[t] = b_h[t]; }

    // W_h -> fp16 padded [o][k]
    {
        int fp = t & 63, og = t >> 6;   // og 0..3, 32 rows each
#pragma unroll
        for (int ii = 0; ii < 32; ii++) {
            int o = og * 32 + ii;
            float2 wv = *(const float2*)&W_h[(size_t)o * 128 + 2 * fp];
            sWh[o * RSW + fp] = h2u(__float22half2_rn(make_float2(wv.x, wv.y)));
        }
    }

    const int grid = MAIN_GRID;
    int tile = blockIdx.x;

    // idx prologue: slot0 = tile, slot1 = tile+grid (64 ints per tile)
    if (t < 64) {
        int n = (tile * 2 + (t >> 5)) & (NN - 1);
        s_idx[t] = idx[n * KK + (t & 31)];
        int t1 = tile + grid;
        if (t1 < NT2) {
            int n1 = (t1 * 2 + (t >> 5)) & (NN - 1);
            s_idx[64 + t] = idx[n1 * KK + (t & 31)];
        }
    }
    __syncthreads();

    // mma mapping + hoisted B fragments (loop-invariant)
    int pt_m = w & 1;
    int nq = w >> 1;
    uint32_t a_base[2];
#pragma unroll
    for (int mt = 0; mt < 2; mt++) {
        int arow = pt_m * 32 + mt * 16 + (lane & 15);
        a_base[mt] = sbase + S_A0 + arow * RSB + ((lane >> 4) << 4);
    }
    uint32_t breg[8][2][4];
    {
        uint32_t b_base[2];
#pragma unroll
        for (int g = 0; g < 2; g++) {
            int brow = nq * 32 + g * 16 + (lane & 7) + ((lane >> 4) << 3);
            b_base[g] = sbase + S_WH + brow * RSB + (((lane >> 3) & 1) << 4);
        }
#pragma unroll
        for (int ks = 0; ks < 8; ks++)
#pragma unroll
            for (int g = 0; g < 2; g++)
                LDSM_X4(breg[ks][g][0], breg[ks][g][1], breg[ks][g][2], breg[ks][g][3],
                        b_base[g] + (uint32_t)ks * 32);
    }

    // prologue gather: tile0 (4 rows x 8 halves per thread, uint4)
    uint4 vreg[4];
    uint4 ctrq;
    {
        int p = tile * 2 + ptg;
        int b = p >> 12;
        ctrq = *(const uint4*)&g_ctr_h[(size_t)p * FD + 8 * fo];
        const __half* nbB = g_nbr_h + (size_t)b * NN * FD + 8 * fo;
#pragma unroll
        for (int qi = 0; qi < 4; qi++)
            vreg[qi] = *(const uint4*)&nbB[(size_t)s_idx[rowb + qi] * FD];
    }

    int it = 0;
    for (; tile < NT2; tile += grid, it++) {
        uint32_t aoff = (it & 1) ? 17408u : 0u;

        // ---- STS: fuse in fp16 (add + relu), uint4 stores ----
        {
            __half2 z = __float2half2_rn(0.f);
            __half2 c0 = *(__half2*)&ctrq.x;
            __half2 c1 = *(__half2*)&ctrq.y;
            __half2 c2 = *(__half2*)&ctrq.z;
            __half2 c3 = *(__half2*)&ctrq.w;
#pragma unroll
            for (int qi = 0; qi < 4; qi++) {
                __half2 u0 = __hmax2(__hadd2(c0, *(__half2*)&vreg[qi].x), z);
                __half2 u1 = __hmax2(__hadd2(c1, *(__half2*)&vreg[qi].y), z);
                __half2 u2 = __hmax2(__hadd2(c2, *(__half2*)&vreg[qi].z), z);
                __half2 u3 = __hmax2(__hadd2(c3, *(__half2*)&vreg[qi].w), z);
                uint4 st;
                st.x = h2u(u0); st.y = h2u(u1); st.z = h2u(u2); st.w = h2u(u3);
                *(uint4*)(smem + S_A0 + aoff + (rowb + qi) * RSB + fo * 16) = st;
            }
        }
        __syncthreads();   // the only barrier per tile

        // ---- idx prefetch tile+2*grid into slot (it&1) ----
        {
            int t2 = tile + 2 * grid;
            if (t < 64 && t2 < NT2) {
                int n = (t2 * 2 + (t >> 5)) & (NN - 1);
                s_idx[(it & 1) * 64 + t] = idx[n * KK + (t & 31)];
            }
        }
        // ---- gather tile+grid (hidden under MMA) ----
        int nt = tile + grid;
        uint4 ctr_next;
        if (nt < NT2) {
            int p = nt * 2 + ptg;
            int b = p >> 12;
            ctr_next = *(const uint4*)&g_ctr_h[(size_t)p * FD + 8 * fo];
            const __half* nbB = g_nbr_h + (size_t)b * NN * FD + 8 * fo;
            const int* si = s_idx + ((it + 1) & 1) * 64 + rowb;
#pragma unroll
            for (int qi = 0; qi < 4; qi++)
                vreg[qi] = *(const uint4*)&nbB[(size_t)si[qi] * FD];
        }

        // ---- MMA: A from smem (LDSM), B from registers ----
        float acc[2][4][4];
#pragma unroll
        for (int mt = 0; mt < 2; mt++)
#pragma unroll
            for (int j = 0; j < 4; j++)
#pragma unroll
                for (int r = 0; r < 4; r++) acc[mt][j][r] = 0.f;

#pragma unroll
        for (int ks = 0; ks < 8; ks++) {
            uint32_t koff = (uint32_t)ks * 32 + aoff;
            uint32_t ah[2][4];
#pragma unroll
            for (int mt = 0; mt < 2; mt++)
                LDSM_X4(ah[mt][0], ah[mt][1], ah[mt][2], ah[mt][3], a_base[mt] + koff);
#pragma unroll
            for (int mt = 0; mt < 2; mt++)
#pragma unroll
                for (int g = 0; g < 2; g++) {
                    MMA_F16_F32(acc[mt][g * 2 + 0], ah[mt], breg[ks][g][0], breg[ks][g][1]);
                    MMA_F16_F32(acc[mt][g * 2 + 1], ah[mt], breg[ks][g][2], breg[ks][g][3]);
                }
        }

        // ---- pool: relu(d*sh+bh), mean over 32 rows -> g_pooled ----
        {
            int p = tile * 2 + pt_m;
#pragma unroll
            for (int j = 0; j < 4; j++) {
                int col0 = nq * 32 + j * 8 + 2 * (lane & 3);
                float sc0 = s_sh[col0], sc1 = s_sh[col0 + 1];
                float bb0 = s_bh[col0], bb1 = s_bh[col0 + 1];
                float v0 = fmaxf(acc[0][j][0] * sc0 + bb0, 0.f)
                         + fmaxf(acc[0][j][2] * sc0 + bb0, 0.f)
                         + fmaxf(acc[1][j][0] * sc0 + bb0, 0.f)
                         + fmaxf(acc[1][j][2] * sc0 + bb0, 0.f);
                float v1 = fmaxf(acc[0][j][1] * sc1 + bb1, 0.f)
                         + fmaxf(acc[0][j][3] * sc1 + bb1, 0.f)
                         + fmaxf(acc[1][j][1] * sc1 + bb1, 0.f)
                         + fmaxf(acc[1][j][3] * sc1 + bb1, 0.f);
#pragma unroll
                for (int off = 4; off < 32; off <<= 1) {
                    v0 += __shfl_xor_sync(0xffffffffu, v0, off);
                    v1 += __shfl_xor_sync(0xffffffffu, v1, off);
                }
                if (lane < 4) {
                    *(float2*)&g_pooled[(size_t)p * DHH + nq * 32 + j * 8 + lane * 2] =
                        make_float2(v0 * (1.f / KK), v1 * (1.f / KK));
                }
            }
        }
        ctrq = ctr_next;
    }
}

// ---------------------------------------------------------------------------
// Kernel 3: final MLP epilogue. 128 points per block (W_f amortized 4x).
// ---------------------------------------------------------------------------
#define EPI_SWF (128 * 68)
#define EPI_SPOOL (32 * 129)
#define EPI_SOUT (64 * 33)
#define EPI_SMEM_BYTES ((EPI_SWF + EPI_SPOOL + EPI_SOUT) * 4)

__global__ void __launch_bounds__(256) epilogue_kernel(
    const float* __restrict__ W_f,
    const float* __restrict__ s_f, const float* __restrict__ b_f,
    const float* __restrict__ features,
    float* __restrict__ out)
{
    extern __shared__ float sm[];
    float* sWf = sm;
    float* sPool = sWf + EPI_SWF;
    float* sOutE = sPool + EPI_SPOOL;

    int t = threadIdx.x;

    for (int e = t; e < 64 * 128; e += 256) {
        int c = e >> 7, i = e & 127;
        sWf[i * 68 + c] = W_f[e];
    }

#pragma unroll 1
    for (int g = 0; g < 4; g++) {
        int p0 = blockIdx.x * 128 + g * 32;
        int b = p0 >> 12;
        int n0 = p0 & (NN - 1);

        __syncthreads();  // previous group's readers done / sWf ready
        for (int e = t; e < 32 * 128; e += 256) {
            int np = e >> 7, i = e & 127;
            sPool[np * 129 + i] = g_pooled[(size_t)p0 * DHH + e];
        }
        __syncthreads();

        {
            int np = t & 31;
            int c0 = (t >> 5) << 3;
            float acc[8];
#pragma unroll
            for (int j = 0; j < 8; j++) acc[j] = 0.f;
#pragma unroll 16
            for (int i = 0; i < 128; i++) {
                float a = sPool[np * 129 + i];
                const float4* wp = (const float4*)&sWf[i * 68 + c0];
                float4 w0 = wp[0], w1 = wp[1];
                acc[0] += a * w0.x; acc[1] += a * w0.y;
                acc[2] += a * w0.z; acc[3] += a * w0.w;
                acc[4] += a * w1.x; acc[5] += a * w1.y;
                acc[6] += a * w1.z; acc[7] += a * w1.w;
            }
#pragma unroll
            for (int j = 0; j < 8; j++) {
                int c = c0 + j;
                sOutE[c * 33 + np] = fmaxf(acc[j] * __ldg(&s_f[c]) + __ldg(&b_f[c]), 0.f);
            }
        }
        __syncthreads();

        for (int e = t; e < 64 * 32; e += 256) {
            int c = e >> 5, np = e & 31;
            size_t o = (size_t)b * CC * NN + (size_t)c * NN + n0 + np;
            out[o] = sOutE[c * 33 + np] + features[o];
        }
    }
}

// ---------------------------------------------------------------------------
extern "C" void kernel_launch(void* const* d_in, const int* in_sizes, int n_in,
                              void* d_out, int out_size)
{
    const float* xyz      = (const float*)d_in[0];
    const float* features = (const float*)d_in[1];
    const int*   idx      = (const int*)d_in[2];
    const float* W_gu     = (const float*)d_in[3];
    const float* s_gu     = (const float*)d_in[4];
    const float* b_gu     = (const float*)d_in[5];
    const float* W_gv     = (const float*)d_in[6];
    const float* s_gv     = (const float*)d_in[7];
    const float* b_gv     = (const float*)d_in[8];
    const float* W_h      = (const float*)d_in[9];
    const float* s_h      = (const float*)d_in[10];
    const float* b_h      = (const float*)d_in[11];
    const float* W_f      = (const float*)d_in[12];
    const float* s_f      = (const float*)d_in[13];
    const float* b_f      = (const float*)d_in[14];

    float* out = (float*)d_out;
    float* out_feat = out;
    float* out_xyz = nullptr;
    const size_t xyz_elems = (size_t)BB * NN * 3;
    const size_t feat_elems = (size_t)BB * CC * NN;

    if ((size_t)out_size == xyz_elems + feat_elems) {
        out_xyz = out;
        out_feat = out + xyz_elems;
    }

    cudaFuncSetAttribute(main_kernel,
                         cudaFuncAttributeMaxDynamicSharedMemorySize, MAIN_SMEM);
    cudaFuncSetAttribute(epilogue_kernel,
                         cudaFuncAttributeMaxDynamicSharedMemorySize, EPI_SMEM_BYTES);

    precompute_kernel<<<BN / 32, 256>>>(xyz, features, W_gu, W_gv,
                                        s_gu, b_gu, s_gv, b_gv, out_xyz);
    main_kernel<<<MAIN_GRID, 256, MAIN_SMEM>>>(idx, W_h, s_h, b_h);
    epilogue_kernel<<<BN / 128, 256, EPI_SMEM_BYTES>>>(W_f, s_f, b_f, features,
                                                       out_feat);
}

// round 13
// speedup vs baseline: 1.0195x; 1.0195x over previous
#include <cuda_runtime.h>
#include <cuda_fp16.h>
#include <cstdint>

// Problem constants
#define BB 4
#define NN 4096
#define KK 32
#define CC 64
#define FD 128
#define DHH 128
#define BN (BB * NN)
#define NT2 (BN / 2)           // M=64 tiles: 2 points per tile

// Scratch (no cudaMalloc allowed)
__device__ __half g_ctr_h[(size_t)BN * FD];   // h(ctr*s + b)
__device__ __half g_nbr_h[(size_t)BN * FD];   // h(v*s)
__device__ float  g_pooled[(size_t)BN * DHH];

// ---------------------------------------------------------------------------
// PTX helpers — baseline sm_80+ instructions only (compute_103-safe).
// ---------------------------------------------------------------------------
__device__ __forceinline__ uint32_t smem_u32(const void* p) {
    uint32_t a;
    asm("{ .reg .u64 t; cvta.to.shared.u64 t, %1; cvt.u32.u64 %0, t; }"
        : "=r"(a) : "l"(p));
    return a;
}

#define LDSM_X4(r0, r1, r2, r3, addr)                                        \
    asm volatile("ldmatrix.sync.aligned.m8n8.x4.shared.b16 {%0,%1,%2,%3}, [%4];" \
                 : "=r"(r0), "=r"(r1), "=r"(r2), "=r"(r3) : "r"(addr))

#define MMA_F16_F32(d, a, b0, b1)                                            \
    asm volatile("mma.sync.aligned.m16n8k16.row.col.f32.f16.f16.f32 "        \
                 "{%0,%1,%2,%3}, {%4,%5,%6,%7}, {%8,%9}, {%0,%1,%2,%3};"     \
                 : "+f"((d)[0]), "+f"((d)[1]), "+f"((d)[2]), "+f"((d)[3])    \
                 : "r"((a)[0]), "r"((a)[1]), "r"((a)[2]), "r"((a)[3]),       \
                   "r"(b0), "r"(b1))

__device__ __forceinline__ uint32_t h2u(__half2 h) { return *(uint32_t*)&h; }

// ---------------------------------------------------------------------------
// Kernel 1: precompute pre-scaled fp16 tables (512 blocks, 32 pts each).
//   g_ctr_h[p][f] = h( (U1|Gv)[f]*s[f] + b[f] )
//   g_nbr_h[p][f] = h( (U2|Gv)[f]*s[f] )
// Also performs the xyz passthrough copy (replaces separate memcpy).
// ---------------------------------------------------------------------------
#define WGV_S 68
__global__ void __launch_bounds__(256) precompute_kernel(
    const float* __restrict__ xyz, const float* __restrict__ features,
    const float* __restrict__ W_gu, const float* __restrict__ W_gv,
    const float* __restrict__ s_gu, const float* __restrict__ b_gu,
    const float* __restrict__ s_gv, const float* __restrict__ b_gv,
    float* __restrict__ out_xyz)
{
    __shared__ float sWgv[64 * WGV_S];
    __shared__ float sWgu[64 * 6];
    __shared__ float sF[64 * 33];
    __shared__ float sXyz[32 * 3];
    __shared__ float sOut[32 * 132];
    __shared__ float sS[128], sB[128];

    int t = threadIdx.x;
    int p0 = blockIdx.x * 32;
    int b = p0 >> 12;
    int n0 = p0 & (NN - 1);

    // xyz passthrough (independent of the rest)
    if (out_xyz) {
        for (int e = blockIdx.x * 256 + t; e < BB * NN * 3; e += gridDim.x * 256)
            out_xyz[e] = xyz[e];
    }

    for (int e = t; e < 64 * 64; e += 256)
        sWgv[(e & 63) * WGV_S + (e >> 6)] = W_gv[e];
    for (int e = t; e < 64 * 6; e += 256)
        sWgu[e] = W_gu[e];
    for (int e = t; e < 64 * 32; e += 256) {
        int c = e >> 5, np = e & 31;
        sF[c * 33 + np] = features[(size_t)b * CC * NN + (size_t)c * NN + n0 + np];
    }
    for (int e = t; e < 96; e += 256)
        sXyz[e] = xyz[(size_t)p0 * 3 + e];
    if (t < 64) { sS[t] = s_gu[t]; sB[t] = b_gu[t]; }
    else if (t < 128) { sS[t] = s_gv[t - 64]; sB[t] = b_gv[t - 64]; }
    __syncthreads();

    // Gv: thread (np = t&31, o0 = (t>>5)*8)
    {
        int np = t & 31;
        int o0 = (t >> 5) << 3;
        float acc[8];
#pragma unroll
        for (int j = 0; j < 8; j++) acc[j] = 0.f;
#pragma unroll 16
        for (int c = 0; c < 64; c++) {
            float a = sF[c * 33 + np];
            const float4* wp = (const float4*)&sWgv[c * WGV_S + o0];
            float4 w0 = wp[0], w1 = wp[1];
            acc[0] += a * w0.x; acc[1] += a * w0.y;
            acc[2] += a * w0.z; acc[3] += a * w0.w;
            acc[4] += a * w1.x; acc[5] += a * w1.y;
            acc[6] += a * w1.z; acc[7] += a * w1.w;
        }
#pragma unroll
        for (int j = 0; j < 8; j++)
            sOut[np * 132 + 64 + o0 + j] = acc[j];
    }
    // U1 into cols 0..63
    for (int e = t; e < 32 * 64; e += 256) {
        int np = e >> 6, o = e & 63;
        float x0 = sXyz[np * 3], x1 = sXyz[np * 3 + 1], x2 = sXyz[np * 3 + 2];
        sOut[np * 132 + o] = sWgu[o * 6 + 0] * x0 + sWgu[o * 6 + 1] * x1 + sWgu[o * 6 + 2] * x2;
    }
    __syncthreads();
    // write ctr table: scale + bias, fp16
    for (int e = t * 8; e < 32 * 128; e += 2048) {
        int np = e >> 7, f = e & 127;
        const float* src = &sOut[np * 132 + f];
        float4 x0 = *(const float4*)src, x1 = *(const float4*)(src + 4);
        float4 s0 = *(const float4*)&sS[f], s1 = *(const float4*)&sS[f + 4];
        float4 c0 = *(const float4*)&sB[f], c1 = *(const float4*)&sB[f + 4];
        uint4 o;
        o.x = h2u(__float22half2_rn(make_float2(x0.x * s0.x + c0.x, x0.y * s0.y + c0.y)));
        o.y = h2u(__float22half2_rn(make_float2(x0.z * s0.z + c0.z, x0.w * s0.w + c0.w)));
        o.z = h2u(__float22half2_rn(make_float2(x1.x * s1.x + c1.x, x1.y * s1.y + c1.y)));
        o.w = h2u(__float22half2_rn(make_float2(x1.z * s1.z + c1.z, x1.w * s1.w + c1.w)));
        *(uint4*)&g_ctr_h[(size_t)p0 * FD + e] = o;
    }
    __syncthreads();
    // overwrite cols 0..63 with U2
    for (int e = t; e < 32 * 64; e += 256) {
        int np = e >> 6, o = e & 63;
        float x0 = sXyz[np * 3], x1 = sXyz[np * 3 + 1], x2 = sXyz[np * 3 + 2];
        sOut[np * 132 + o] = sWgu[o * 6 + 3] * x0 + sWgu[o * 6 + 4] * x1 + sWgu[o * 6 + 5] * x2;
    }
    __syncthreads();
    // write nbr table: scale only, fp16
    for (int e = t * 8; e < 32 * 128; e += 2048) {
        int np = e >> 7, f = e & 127;
        const float* src = &sOut[np * 132 + f];
        float4 x0 = *(const float4*)src, x1 = *(const float4*)(src + 4);
        float4 s0 = *(const float4*)&sS[f], s1 = *(const float4*)&sS[f + 4];
        uint4 o;
        o.x = h2u(__float22half2_rn(make_float2(x0.x * s0.x, x0.y * s0.y)));
        o.y = h2u(__float22half2_rn(make_float2(x0.z * s0.z, x0.w * s0.w)));
        o.z = h2u(__float22half2_rn(make_float2(x1.x * s1.x, x1.y * s1.y)));
        o.w = h2u(__float22half2_rn(make_float2(x1.z * s1.z, x1.w * s1.w)));
        *(uint4*)&g_nbr_h[(size_t)p0 * FD + e] = o;
    }
}

// ---------------------------------------------------------------------------
// Kernel 2 (main): R10's measured-best config. 256-thread CTAs, M=64 tiles
// (2 points), grid 304, 2 CTAs/SM. B fragments hoisted in registers,
// double-buffered A smem, one barrier/tile. uint2 gather (8 rows x 4 halves).
// ---------------------------------------------------------------------------
#define MAIN_GRID 304
#define RSB 272
#define RSW 68
#define S_WH 0                       // W_h fp16       34816
#define S_A0 34816                   // A buf 0        17408
#define S_A1 52224                   // A buf 1        17408
#define S_IDX 69632                  // 2x64 ints      512
#define S_SH  70144                  // s_h            512
#define S_BH  70656                  // b_h            512
#define MAIN_SMEM 71168

__global__ void __launch_bounds__(256, 2) main_kernel(
    const int* __restrict__ idx,
    const float* __restrict__ W_h,
    const float* __restrict__ s_h, const float* __restrict__ b_h)
{
    extern __shared__ __align__(16) char smem[];
    uint32_t sbase = smem_u32(smem);
    uint32_t* sWh = (uint32_t*)(smem + S_WH);
    int*   s_idx = (int*)(smem + S_IDX);
    float* s_sh = (float*)(smem + S_SH);
    float* s_bh = (float*)(smem + S_BH);

    int t = threadIdx.x;
    int lane = t & 31;
    int w = t >> 5;

    // gather mapping: feature quad fq (halves 4fq..4fq+3), row group rg (8 rows)
    int fq = t & 31;
    int rg = t >> 5;            // 0..7 -> rows rg*8 .. rg*8+7
    int ptg = rg >> 2;          // point of this row group (0/1)

    if (t < 128) { s_sh[t] = s_h[t]; s_bh[t] = b_h[t]; }

    // W_h -> fp16 padded [o][k]
    {
        int fp = t & 63, og = t >> 6;   // og 0..3, 32 rows each
#pragma unroll
        for (int ii = 0; ii < 32; ii++) {
            int o = og * 32 + ii;
            float2 wv = *(const float2*)&W_h[(size_t)o * 128 + 2 * fp];
            sWh[o * RSW + fp] = h2u(__float22half2_rn(make_float2(wv.x, wv.y)));
        }
    }

    const int grid = MAIN_GRID;
    int tile = blockIdx.x;

    // idx prologue: slot0 = tile, slot1 = tile+grid (64 ints per tile)
    if (t < 64) {
        int n = (tile * 2 + (t >> 5)) & (NN - 1);
        s_idx[t] = idx[n * KK + (t & 31)];
        int t1 = tile + grid;
        if (t1 < NT2) {
            int n1 = (t1 * 2 + (t >> 5)) & (NN - 1);
            s_idx[64 + t] = idx[n1 * KK + (t & 31)];
        }
    }
    __syncthreads();

    // mma mapping + hoisted B fragments (loop-invariant)
    int pt_m = w & 1;
    int nq = w >> 1;
    uint32_t a_base[2];
#pragma unroll
    for (int mt = 0; mt < 2; mt++) {
        int arow = pt_m * 32 + mt * 16 + (lane & 15);
        a_base[mt] = sbase + S_A0 + arow * RSB + ((lane >> 4) << 4);
    }
    uint32_t breg[8][2][4];
    {
        uint32_t b_base[2];
#pragma unroll
        for (int g = 0; g < 2; g++) {
            int brow = nq * 32 + g * 16 + (lane & 7) + ((lane >> 4) << 3);
            b_base[g] = sbase + S_WH + brow * RSB + (((lane >> 3) & 1) << 4);
        }
#pragma unroll
        for (int ks = 0; ks < 8; ks++)
#pragma unroll
            for (int g = 0; g < 2; g++)
                LDSM_X4(breg[ks][g][0], breg[ks][g][1], breg[ks][g][2], breg[ks][g][3],
                        b_base[g] + (uint32_t)ks * 32);
    }

    // prologue gather: tile0 (8 rows x 4 halves per thread, uint2)
    uint2 vreg[8];
    uint2 ctrq;
    {
        int p = tile * 2 + ptg;
        int b = p >> 12;
        ctrq = *(const uint2*)&g_ctr_h[(size_t)p * FD + 4 * fq];
        const __half* nbB = g_nbr_h + (size_t)b * NN * FD + 4 * fq;
        const int* si = s_idx + rg * 8;
#pragma unroll
        for (int qi = 0; qi < 8; qi++)
            vreg[qi] = *(const uint2*)&nbB[(size_t)si[qi] * FD];
    }

    int it = 0;
    for (; tile < NT2; tile += grid, it++) {
        uint32_t aoff = (it & 1) ? 17408u : 0u;
        uint32_t* sA = (uint32_t*)(smem + S_A0 + aoff);

        // ---- STS: fuse in fp16 (add + relu) ----
        {
            int rowb = rg * 8;
            __half2 z = __float2half2_rn(0.f);
            __half2 c0 = *(__half2*)&ctrq.x;
            __half2 c1 = *(__half2*)&ctrq.y;
#pragma unroll
            for (int qi = 0; qi < 8; qi++) {
                __half2 u0 = __hmax2(__hadd2(c0, *(__half2*)&vreg[qi].x), z);
                __half2 u1 = __hmax2(__hadd2(c1, *(__half2*)&vreg[qi].y), z);
                uint2 st; st.x = h2u(u0); st.y = h2u(u1);
                *(uint2*)&sA[(rowb + qi) * RSW + 2 * fq] = st;
            }
        }
        __syncthreads();   // the only barrier per tile

        // ---- idx prefetch tile+2*grid into slot (it&1) ----
        {
            int t2 = tile + 2 * grid;
            if (t < 64 && t2 < NT2) {
                int n = (t2 * 2 + (t >> 5)) & (NN - 1);
                s_idx[(it & 1) * 64 + t] = idx[n * KK + (t & 31)];
            }
        }
        // ---- gather tile+grid (hidden under MMA) ----
        int nt = tile + grid;
        uint2 ctr_next;
        if (nt < NT2) {
            int p = nt * 2 + ptg;
            int b = p >> 12;
            ctr_next = *(const uint2*)&g_ctr_h[(size_t)p * FD + 4 * fq];
            const __half* nbB = g_nbr_h + (size_t)b * NN * FD + 4 * fq;
            const int* si = s_idx + ((it + 1) & 1) * 64 + rg * 8;
#pragma unroll
            for (int qi = 0; qi < 8; qi++)
                vreg[qi] = *(const uint2*)&nbB[(size_t)si[qi] * FD];
        }

        // ---- MMA: A from smem (LDSM), B from registers ----
        float acc[2][4][4];
#pragma unroll
        for (int mt = 0; mt < 2; mt++)
#pragma unroll
            for (int j = 0; j < 4; j++)
#pragma unroll
                for (int r = 0; r < 4; r++) acc[mt][j][r] = 0.f;

#pragma unroll
        for (int ks = 0; ks < 8; ks++) {
            uint32_t koff = (uint32_t)ks * 32 + aoff;
            uint32_t ah[2][4];
#pragma unroll
            for (int mt = 0; mt < 2; mt++)
                LDSM_X4(ah[mt][0], ah[mt][1], ah[mt][2], ah[mt][3], a_base[mt] + koff);
#pragma unroll
            for (int mt = 0; mt < 2; mt++)
#pragma unroll
                for (int g = 0; g < 2; g++) {
                    MMA_F16_F32(acc[mt][g * 2 + 0], ah[mt], breg[ks][g][0], breg[ks][g][1]);
                    MMA_F16_F32(acc[mt][g * 2 + 1], ah[mt], breg[ks][g][2], breg[ks][g][3]);
                }
        }

        // ---- pool: relu(d*sh+bh), mean over 32 rows -> g_pooled ----
        {
            int p = tile * 2 + pt_m;
#pragma unroll
            for (int j = 0; j < 4; j++) {
                int col0 = nq * 32 + j * 8 + 2 * (lane & 3);
                float sc0 = s_sh[col0], sc1 = s_sh[col0 + 1];
                float bb0 = s_bh[col0], bb1 = s_bh[col0 + 1];
                float v0 = fmaxf(acc[0][j][0] * sc0 + bb0, 0.f)
                         + fmaxf(acc[0][j][2] * sc0 + bb0, 0.f)
                         + fmaxf(acc[1][j][0] * sc0 + bb0, 0.f)
                         + fmaxf(acc[1][j][2] * sc0 + bb0, 0.f);
                float v1 = fmaxf(acc[0][j][1] * sc1 + bb1, 0.f)
                         + fmaxf(acc[0][j][3] * sc1 + bb1, 0.f)
                         + fmaxf(acc[1][j][1] * sc1 + bb1, 0.f)
                         + fmaxf(acc[1][j][3] * sc1 + bb1, 0.f);
#pragma unroll
                for (int off = 4; off < 32; off <<= 1) {
                    v0 += __shfl_xor_sync(0xffffffffu, v0, off);
                    v1 += __shfl_xor_sync(0xffffffffu, v1, off);
                }
                if (lane < 4) {
                    *(float2*)&g_pooled[(size_t)p * DHH + nq * 32 + j * 8 + lane * 2] =
                        make_float2(v0 * (1.f / KK), v1 * (1.f / KK));
                }
            }
        }
        ctrq = ctr_next;
    }
}

// ---------------------------------------------------------------------------
// Kernel 3: final MLP epilogue. 128 points per block (W_f amortized 4x).
// ---------------------------------------------------------------------------
#define EPI_SWF (128 * 68)
#define EPI_SPOOL (32 * 129)
#define EPI_SOUT (64 * 33)
#define EPI_SMEM_BYTES ((EPI_SWF + EPI_SPOOL + EPI_SOUT) * 4)

__global__ void __launch_bounds__(256) epilogue_kernel(
    const float* __restrict__ W_f,
    const float* __restrict__ s_f, const float* __restrict__ b_f,
    const float* __restrict__ features,
    float* __restrict__ out)
{
    extern __shared__ float sm[];
    float* sWf = sm;
    float* sPool = sWf + EPI_SWF;
    float* sOutE = sPool + EPI_SPOOL;

    int t = threadIdx.x;

    for (int e = t; e < 64 * 128; e += 256) {
        int c = e >> 7, i = e & 127;
        sWf[i * 68 + c] = W_f[e];
    }

#pragma unroll 1
    for (int g = 0; g < 4; g++) {
        int p0 = blockIdx.x * 128 + g * 32;
        int b = p0 >> 12;
        int n0 = p0 & (NN - 1);

        __syncthreads();  // previous group's readers done / sWf ready
        for (int e = t; e < 32 * 128; e += 256) {
            int np = e >> 7, i = e & 127;
            sPool[np * 129 + i] = g_pooled[(size_t)p0 * DHH + e];
        }
        __syncthreads();

        {
            int np = t & 31;
            int c0 = (t >> 5) << 3;
            float acc[8];
#pragma unroll
            for (int j = 0; j < 8; j++) acc[j] = 0.f;
#pragma unroll 16
            for (int i = 0; i < 128; i++) {
                float a = sPool[np * 129 + i];
                const float4* wp = (const float4*)&sWf[i * 68 + c0];
                float4 w0 = wp[0], w1 = wp[1];
                acc[0] += a * w0.x; acc[1] += a * w0.y;
                acc[2] += a * w0.z; acc[3] += a * w0.w;
                acc[4] += a * w1.x; acc[5] += a * w1.y;
                acc[6] += a * w1.z; acc[7] += a * w1.w;
            }
#pragma unroll
            for (int j = 0; j < 8; j++) {
                int c = c0 + j;
                sOutE[c * 33 + np] = fmaxf(acc[j] * __ldg(&s_f[c]) + __ldg(&b_f[c]), 0.f);
            }
        }
        __syncthreads();

        for (int e = t; e < 64 * 32; e += 256) {
            int c = e >> 5, np = e & 31;
            size_t o = (size_t)b * CC * NN + (size_t)c * NN + n0 + np;
            out[o] = sOutE[c * 33 + np] + features[o];
        }
    }
}

// ---------------------------------------------------------------------------
extern "C" void kernel_launch(void* const* d_in, const int* in_sizes, int n_in,
                              void* d_out, int out_size)
{
    const float* xyz      = (const float*)d_in[0];
    const float* features = (const float*)d_in[1];
    const int*   idx      = (const int*)d_in[2];
    const float* W_gu     = (const float*)d_in[3];
    const float* s_gu     = (const float*)d_in[4];
    const float* b_gu     = (const float*)d_in[5];
    const float* W_gv     = (const float*)d_in[6];
    const float* s_gv     = (const float*)d_in[7];
    const float* b_gv     = (const float*)d_in[8];
    const float* W_h      = (const float*)d_in[9];
    const float* s_h      = (const float*)d_in[10];
    const float* b_h      = (const float*)d_in[11];
    const float* W_f      = (const float*)d_in[12];
    const float* s_f      = (const float*)d_in[13];
    const float* b_f      = (const float*)d_in[14];

    float* out = (float*)d_out;
    float* out_feat = out;
    float* out_xyz = nullptr;
    const size_t xyz_elems = (size_t)BB * NN * 3;
    const size_t feat_elems = (size_t)BB * CC * NN;

    if ((size_t)out_size == xyz_elems + feat_elems) {
        out_xyz = out;
        out_feat = out + xyz_elems;
    }

    cudaFuncSetAttribute(main_kernel,
                         cudaFuncAttributeMaxDynamicSharedMemorySize, MAIN_SMEM);
    cudaFuncSetAttribute(epilogue_kernel,
                         cudaFuncAttributeMaxDynamicSharedMemorySize, EPI_SMEM_BYTES);

    precompute_kernel<<<BN / 32, 256>>>(xyz, features, W_gu, W_gv,
                                        s_gu, b_gu, s_gv, b_gv, out_xyz);
    main_kernel<<<MAIN_GRID, 256, MAIN_SMEM>>>(idx, W_h, s_h, b_h);
    epilogue_kernel<<<BN / 128, 256, EPI_SMEM_BYTES>>>(W_f, s_f, b_f, features,
                                                       out_feat);
}

// round 14
// speedup vs baseline: 1.0646x; 1.0442x over previous
#include <cuda_runtime.h>
#include <cuda_fp16.h>
#include <cstdint>

// Problem constants
#define BB 4
#define NN 4096
#define KK 32
#define CC 64
#define FD 128
#define DHH 128
#define BN (BB * NN)
#define NT2 (BN / 2)           // M=64 tiles: 2 points per tile

// Scratch (no cudaMalloc allowed)
__device__ __half g_ctr_h[(size_t)BN * FD];   // h(ctr*s + b)
__device__ __half g_nbr_h[(size_t)BN * FD];   // h(v*s)
__device__ float  g_pooled[(size_t)BN * DHH];

// ---------------------------------------------------------------------------
// PTX helpers — baseline sm_80+ instructions only (compute_103-safe).
// ---------------------------------------------------------------------------
__device__ __forceinline__ uint32_t smem_u32(const void* p) {
    uint32_t a;
    asm("{ .reg .u64 t; cvta.to.shared.u64 t, %1; cvt.u32.u64 %0, t; }"
        : "=r"(a) : "l"(p));
    return a;
}

#define LDSM_X4(r0, r1, r2, r3, addr)                                        \
    asm volatile("ldmatrix.sync.aligned.m8n8.x4.shared.b16 {%0,%1,%2,%3}, [%4];" \
                 : "=r"(r0), "=r"(r1), "=r"(r2), "=r"(r3) : "r"(addr))

// fp16-accumulate MMA: D(2 packed regs) = A(4) * B(2) + D  — full-rate HMMA
#define MMA_F16_F16(d, a, b0, b1)                                            \
    asm volatile("mma.sync.aligned.m16n8k16.row.col.f16.f16.f16.f16 "        \
                 "{%0,%1}, {%2,%3,%4,%5}, {%6,%7}, {%0,%1};"                 \
                 : "+r"((d)[0]), "+r"((d)[1])                                \
                 : "r"((a)[0]), "r"((a)[1]), "r"((a)[2]), "r"((a)[3]),       \
                   "r"(b0), "r"(b1))

__device__ __forceinline__ uint32_t h2u(__half2 h) { return *(uint32_t*)&h; }

// ---------------------------------------------------------------------------
// Kernel 1: precompute pre-scaled fp16 tables (512 blocks, 32 pts each).
//   g_ctr_h[p][f] = h( (U1|Gv)[f]*s[f] + b[f] )
//   g_nbr_h[p][f] = h( (U2|Gv)[f]*s[f] )
// Also performs the xyz passthrough copy (replaces separate memcpy).
// ---------------------------------------------------------------------------
#define WGV_S 68
__global__ void __launch_bounds__(256) precompute_kernel(
    const float* __restrict__ xyz, const float* __restrict__ features,
    const float* __restrict__ W_gu, const float* __restrict__ W_gv,
    const float* __restrict__ s_gu, const float* __restrict__ b_gu,
    const float* __restrict__ s_gv, const float* __restrict__ b_gv,
    float* __restrict__ out_xyz)
{
    __shared__ float sWgv[64 * WGV_S];
    __shared__ float sWgu[64 * 6];
    __shared__ float sF[64 * 33];
    __shared__ float sXyz[32 * 3];
    __shared__ float sOut[32 * 132];
    __shared__ float sS[128], sB[128];

    int t = threadIdx.x;
    int p0 = blockIdx.x * 32;
    int b = p0 >> 12;
    int n0 = p0 & (NN - 1);

    // xyz passthrough (independent of the rest)
    if (out_xyz) {
        for (int e = blockIdx.x * 256 + t; e < BB * NN * 3; e += gridDim.x * 256)
            out_xyz[e] = xyz[e];
    }

    for (int e = t; e < 64 * 64; e += 256)
        sWgv[(e & 63) * WGV_S + (e >> 6)] = W_gv[e];
    for (int e = t; e < 64 * 6; e += 256)
        sWgu[e] = W_gu[e];
    for (int e = t; e < 64 * 32; e += 256) {
        int c = e >> 5, np = e & 31;
        sF[c * 33 + np] = features[(size_t)b * CC * NN + (size_t)c * NN + n0 + np];
    }
    for (int e = t; e < 96; e += 256)
        sXyz[e] = xyz[(size_t)p0 * 3 + e];
    if (t < 64) { sS[t] = s_gu[t]; sB[t] = b_gu[t]; }
    else if (t < 128) { sS[t] = s_gv[t - 64]; sB[t] = b_gv[t - 64]; }
    __syncthreads();

    // Gv: thread (np = t&31, o0 = (t>>5)*8)
    {
        int np = t & 31;
        int o0 = (t >> 5) << 3;
        float acc[8];
#pragma unroll
        for (int j = 0; j < 8; j++) acc[j] = 0.f;
#pragma unroll 16
        for (int c = 0; c < 64; c++) {
            float a = sF[c * 33 + np];
            const float4* wp = (const float4*)&sWgv[c * WGV_S + o0];
            float4 w0 = wp[0], w1 = wp[1];
            acc[0] += a * w0.x; acc[1] += a * w0.y;
            acc[2] += a * w0.z; acc[3] += a * w0.w;
            acc[4] += a * w1.x; acc[5] += a * w1.y;
            acc[6] += a * w1.z; acc[7] += a * w1.w;
        }
#pragma unroll
        for (int j = 0; j < 8; j++)
            sOut[np * 132 + 64 + o0 + j] = acc[j];
    }
    // U1 into cols 0..63
    for (int e = t; e < 32 * 64; e += 256) {
        int np = e >> 6, o = e & 63;
        float x0 = sXyz[np * 3], x1 = sXyz[np * 3 + 1], x2 = sXyz[np * 3 + 2];
        sOut[np * 132 + o] = sWgu[o * 6 + 0] * x0 + sWgu[o * 6 + 1] * x1 + sWgu[o * 6 + 2] * x2;
    }
    __syncthreads();
    // write ctr table: scale + bias, fp16
    for (int e = t * 8; e < 32 * 128; e += 2048) {
        int np = e >> 7, f = e & 127;
        const float* src = &sOut[np * 132 + f];
        float4 x0 = *(const float4*)src, x1 = *(const float4*)(src + 4);
        float4 s0 = *(const float4*)&sS[f], s1 = *(const float4*)&sS[f + 4];
        float4 c0 = *(const float4*)&sB[f], c1 = *(const float4*)&sB[f + 4];
        uint4 o;
        o.x = h2u(__float22half2_rn(make_float2(x0.x * s0.x + c0.x, x0.y * s0.y + c0.y)));
        o.y = h2u(__float22half2_rn(make_float2(x0.z * s0.z + c0.z, x0.w * s0.w + c0.w)));
        o.z = h2u(__float22half2_rn(make_float2(x1.x * s1.x + c1.x, x1.y * s1.y + c1.y)));
        o.w = h2u(__float22half2_rn(make_float2(x1.z * s1.z + c1.z, x1.w * s1.w + c1.w)));
        *(uint4*)&g_ctr_h[(size_t)p0 * FD + e] = o;
    }
    __syncthreads();
    // overwrite cols 0..63 with U2
    for (int e = t; e < 32 * 64; e += 256) {
        int np = e >> 6, o = e & 63;
        float x0 = sXyz[np * 3], x1 = sXyz[np * 3 + 1], x2 = sXyz[np * 3 + 2];
        sOut[np * 132 + o] = sWgu[o * 6 + 3] * x0 + sWgu[o * 6 + 4] * x1 + sWgu[o * 6 + 5] * x2;
    }
    __syncthreads();
    // write nbr table: scale only, fp16
    for (int e = t * 8; e < 32 * 128; e += 2048) {
        int np = e >> 7, f = e & 127;
        const float* src = &sOut[np * 132 + f];
        float4 x0 = *(const float4*)src, x1 = *(const float4*)(src + 4);
        float4 s0 = *(const float4*)&sS[f], s1 = *(const float4*)&sS[f + 4];
        uint4 o;
        o.x = h2u(__float22half2_rn(make_float2(x0.x * s0.x, x0.y * s0.y)));
        o.y = h2u(__float22half2_rn(make_float2(x0.z * s0.z, x0.w * s0.w)));
        o.z = h2u(__float22half2_rn(make_float2(x1.x * s1.x, x1.y * s1.y)));
        o.w = h2u(__float22half2_rn(make_float2(x1.z * s1.z, x1.w * s1.w)));
        *(uint4*)&g_nbr_h[(size_t)p0 * FD + e] = o;
    }
}

// ---------------------------------------------------------------------------
// Kernel 2 (main): R13 structure, but fp16-ACCUMULATE MMA (full-rate HMMA).
// 256-thread CTAs, M=64 tiles (2 points), grid 304, 2 CTAs/SM.
// B fragments hoisted in registers, double-buffered A smem, one barrier/tile.
// ---------------------------------------------------------------------------
#define MAIN_GRID 304
#define RSB 272
#define RSW 68
#define S_WH 0                       // W_h fp16       34816
#define S_A0 34816                   // A buf 0        17408
#define S_A1 52224                   // A buf 1        17408
#define S_IDX 69632                  // 2x64 ints      512
#define S_SH  70144                  // s_h            512
#define S_BH  70656                  // b_h            512
#define MAIN_SMEM 71168

__global__ void __launch_bounds__(256, 2) main_kernel(
    const int* __restrict__ idx,
    const float* __restrict__ W_h,
    const float* __restrict__ s_h, const float* __restrict__ b_h)
{
    extern __shared__ __align__(16) char smem[];
    uint32_t sbase = smem_u32(smem);
    uint32_t* sWh = (uint32_t*)(smem + S_WH);
    int*   s_idx = (int*)(smem + S_IDX);
    float* s_sh = (float*)(smem + S_SH);
    float* s_bh = (float*)(smem + S_BH);

    int t = threadIdx.x;
    int lane = t & 31;
    int w = t >> 5;

    // gather mapping: feature quad fq (halves 4fq..4fq+3), row group rg (8 rows)
    int fq = t & 31;
    int rg = t >> 5;            // 0..7 -> rows rg*8 .. rg*8+7
    int ptg = rg >> 2;          // point of this row group (0/1)

    if (t < 128) { s_sh[t] = s_h[t]; s_bh[t] = b_h[t]; }

    // W_h -> fp16 padded [o][k]
    {
        int fp = t & 63, og = t >> 6;   // og 0..3, 32 rows each
#pragma unroll
        for (int ii = 0; ii < 32; ii++) {
            int o = og * 32 + ii;
            float2 wv = *(const float2*)&W_h[(size_t)o * 128 + 2 * fp];
            sWh[o * RSW + fp] = h2u(__float22half2_rn(make_float2(wv.x, wv.y)));
        }
    }

    const int grid = MAIN_GRID;
    int tile = blockIdx.x;

    // idx prologue: slot0 = tile, slot1 = tile+grid (64 ints per tile)
    if (t < 64) {
        int n = (tile * 2 + (t >> 5)) & (NN - 1);
        s_idx[t] = idx[n * KK + (t & 31)];
        int t1 = tile + grid;
        if (t1 < NT2) {
            int n1 = (t1 * 2 + (t >> 5)) & (NN - 1);
            s_idx[64 + t] = idx[n1 * KK + (t & 31)];
        }
    }
    __syncthreads();

    // mma mapping + hoisted B fragments (loop-invariant)
    int pt_m = w & 1;
    int nq = w >> 1;
    uint32_t a_base[2];
#pragma unroll
    for (int mt = 0; mt < 2; mt++) {
        int arow = pt_m * 32 + mt * 16 + (lane & 15);
        a_base[mt] = sbase + S_A0 + arow * RSB + ((lane >> 4) << 4);
    }
    uint32_t breg[8][2][4];
    {
        uint32_t b_base[2];
#pragma unroll
        for (int g = 0; g < 2; g++) {
            int brow = nq * 32 + g * 16 + (lane & 7) + ((lane >> 4) << 3);
            b_base[g] = sbase + S_WH + brow * RSB + (((lane >> 3) & 1) << 4);
        }
#pragma unroll
        for (int ks = 0; ks < 8; ks++)
#pragma unroll
            for (int g = 0; g < 2; g++)
                LDSM_X4(breg[ks][g][0], breg[ks][g][1], breg[ks][g][2], breg[ks][g][3],
                        b_base[g] + (uint32_t)ks * 32);
    }

    // prologue gather: tile0 (8 rows x 4 halves per thread, uint2)
    uint2 vreg[8];
    uint2 ctrq;
    {
        int p = tile * 2 + ptg;
        int b = p >> 12;
        ctrq = *(const uint2*)&g_ctr_h[(size_t)p * FD + 4 * fq];
        const __half* nbB = g_nbr_h + (size_t)b * NN * FD + 4 * fq;
        const int* si = s_idx + rg * 8;
#pragma unroll
        for (int qi = 0; qi < 8; qi++)
            vreg[qi] = *(const uint2*)&nbB[(size_t)si[qi] * FD];
    }

    int it = 0;
    for (; tile < NT2; tile += grid, it++) {
        uint32_t aoff = (it & 1) ? 17408u : 0u;
        uint32_t* sA = (uint32_t*)(smem + S_A0 + aoff);

        // ---- STS: fuse in fp16 (add + relu) ----
        {
            int rowb = rg * 8;
            __half2 z = __float2half2_rn(0.f);
            __half2 c0 = *(__half2*)&ctrq.x;
            __half2 c1 = *(__half2*)&ctrq.y;
#pragma unroll
            for (int qi = 0; qi < 8; qi++) {
                __half2 u0 = __hmax2(__hadd2(c0, *(__half2*)&vreg[qi].x), z);
                __half2 u1 = __hmax2(__hadd2(c1, *(__half2*)&vreg[qi].y), z);
                uint2 st; st.x = h2u(u0); st.y = h2u(u1);
                *(uint2*)&sA[(rowb + qi) * RSW + 2 * fq] = st;
            }
        }
        __syncthreads();   // the only barrier per tile

        // ---- idx prefetch tile+2*grid into slot (it&1) ----
        {
            int t2 = tile + 2 * grid;
            if (t < 64 && t2 < NT2) {
                int n = (t2 * 2 + (t >> 5)) & (NN - 1);
                s_idx[(it & 1) * 64 + t] = idx[n * KK + (t & 31)];
            }
        }
        // ---- gather tile+grid (hidden under MMA) ----
        int nt = tile + grid;
        uint2 ctr_next;
        if (nt < NT2) {
            int p = nt * 2 + ptg;
            int b = p >> 12;
            ctr_next = *(const uint2*)&g_ctr_h[(size_t)p * FD + 4 * fq];
            const __half* nbB = g_nbr_h + (size_t)b * NN * FD + 4 * fq;
            const int* si = s_idx + ((it + 1) & 1) * 64 + rg * 8;
#pragma unroll
            for (int qi = 0; qi < 8; qi++)
                vreg[qi] = *(const uint2*)&nbB[(size_t)si[qi] * FD];
        }

        // ---- MMA: A from smem (LDSM), B from registers, fp16 accumulate ----
        uint32_t accl[2][4][2];
#pragma unroll
        for (int mt = 0; mt < 2; mt++)
#pragma unroll
            for (int j = 0; j < 4; j++) {
                accl[mt][j][0] = 0u; accl[mt][j][1] = 0u;
            }

#pragma unroll
        for (int ks = 0; ks < 8; ks++) {
            uint32_t koff = (uint32_t)ks * 32 + aoff;
            uint32_t ah[2][4];
#pragma unroll
            for (int mt = 0; mt < 2; mt++)
                LDSM_X4(ah[mt][0], ah[mt][1], ah[mt][2], ah[mt][3], a_base[mt] + koff);
#pragma unroll
            for (int mt = 0; mt < 2; mt++)
#pragma unroll
                for (int g = 0; g < 2; g++) {
                    MMA_F16_F16(accl[mt][g * 2 + 0], ah[mt], breg[ks][g][0], breg[ks][g][1]);
                    MMA_F16_F16(accl[mt][g * 2 + 1], ah[mt], breg[ks][g][2], breg[ks][g][3]);
                }
        }

        // ---- pool: unpack fp16 acc, relu(d*sh+bh), mean over 32 rows ----
        {
            int p = tile * 2 + pt_m;
#pragma unroll
            for (int j = 0; j < 4; j++) {
                int col0 = nq * 32 + j * 8 + 2 * (lane & 3);
                float sc0 = s_sh[col0], sc1 = s_sh[col0 + 1];
                float bb0 = s_bh[col0], bb1 = s_bh[col0 + 1];
                float v0 = 0.f, v1 = 0.f;
#pragma unroll
                for (int mt = 0; mt < 2; mt++) {
                    // accl[mt][j][0]: (row r,   cols c0,c1) ; [1]: (row r+8, cols c0,c1)
                    float2 d0 = __half22float2(*(__half2*)&accl[mt][j][0]);
                    float2 d1 = __half22float2(*(__half2*)&accl[mt][j][1]);
                    v0 += fmaxf(d0.x * sc0 + bb0, 0.f) + fmaxf(d1.x * sc0 + bb0, 0.f);
                    v1 += fmaxf(d0.y * sc1 + bb1, 0.f) + fmaxf(d1.y * sc1 + bb1, 0.f);
                }
#pragma unroll
                for (int off = 4; off < 32; off <<= 1) {
                    v0 += __shfl_xor_sync(0xffffffffu, v0, off);
                    v1 += __shfl_xor_sync(0xffffffffu, v1, off);
                }
                if (lane < 4) {
                    *(float2*)&g_pooled[(size_t)p * DHH + nq * 32 + j * 8 + lane * 2] =
                        make_float2(v0 * (1.f / KK), v1 * (1.f / KK));
                }
            }
        }
        ctrq = ctr_next;
    }
}

// ---------------------------------------------------------------------------
// Kernel 3: final MLP epilogue. 128 points per block (W_f amortized 4x).
// ---------------------------------------------------------------------------
#define EPI_SWF (128 * 68)
#define EPI_SPOOL (32 * 129)
#define EPI_SOUT (64 * 33)
#define EPI_SMEM_BYTES ((EPI_SWF + EPI_SPOOL + EPI_SOUT) * 4)

__global__ void __launch_bounds__(256) epilogue_kernel(
    const float* __restrict__ W_f,
    const float* __restrict__ s_f, const float* __restrict__ b_f,
    const float* __restrict__ features,
    float* __restrict__ out)
{
    extern __shared__ float sm[];
    float* sWf = sm;
    float* sPool = sWf + EPI_SWF;
    float* sOutE = sPool + EPI_SPOOL;

    int t = threadIdx.x;

    for (int e = t; e < 64 * 128; e += 256) {
        int c = e >> 7, i = e & 127;
        sWf[i * 68 + c] = W_f[e];
    }

#pragma unroll 1
    for (int g = 0; g < 4; g++) {
        int p0 = blockIdx.x * 128 + g * 32;
        int b = p0 >> 12;
        int n0 = p0 & (NN - 1);

        __syncthreads();  // previous group's readers done / sWf ready
        for (int e = t; e < 32 * 128; e += 256) {
            int np = e >> 7, i = e & 127;
            sPool[np * 129 + i] = g_pooled[(size_t)p0 * DHH + e];
        }
        __syncthreads();

        {
            int np = t & 31;
            int c0 = (t >> 5) << 3;
            float acc[8];
#pragma unroll
            for (int j = 0; j < 8; j++) acc[j] = 0.f;
#pragma unroll 16
            for (int i = 0; i < 128; i++) {
                float a = sPool[np * 129 + i];
                const float4* wp = (const float4*)&sWf[i * 68 + c0];
                float4 w0 = wp[0], w1 = wp[1];
                acc[0] += a * w0.x; acc[1] += a * w0.y;
                acc[2] += a * w0.z; acc[3] += a * w0.w;
                acc[4] += a * w1.x; acc[5] += a * w1.y;
                acc[6] += a * w1.z; acc[7] += a * w1.w;
            }
#pragma unroll
            for (int j = 0; j < 8; j++) {
                int c = c0 + j;
                sOutE[c * 33 + np] = fmaxf(acc[j] * __ldg(&s_f[c]) + __ldg(&b_f[c]), 0.f);
            }
        }
        __syncthreads();

        for (int e = t; e < 64 * 32; e += 256) {
            int c = e >> 5, np = e & 31;
            size_t o = (size_t)b * CC * NN + (size_t)c * NN + n0 + np;
            out[o] = sOutE[c * 33 + np] + features[o];
        }
    }
}

// ---------------------------------------------------------------------------
extern "C" void kernel_launch(void* const* d_in, const int* in_sizes, int n_in,
                              void* d_out, int out_size)
{
    const float* xyz      = (const float*)d_in[0];
    const float* features = (const float*)d_in[1];
    const int*   idx      = (const int*)d_in[2];
    const float* W_gu     = (const float*)d_in[3];
    const float* s_gu     = (const float*)d_in[4];
    const float* b_gu     = (const float*)d_in[5];
    const float* W_gv     = (const float*)d_in[6];
    const float* s_gv     = (const float*)d_in[7];
    const float* b_gv     = (const float*)d_in[8];
    const float* W_h      = (const float*)d_in[9];
    const float* s_h      = (const float*)d_in[10];
    const float* b_h      = (const float*)d_in[11];
    const float* W_f      = (const float*)d_in[12];
    const float* s_f      = (const float*)d_in[13];
    const float* b_f      = (const float*)d_in[14];

    float* out = (float*)d_out;
    float* out_feat = out;
    float* out_xyz = nullptr;
    const size_t xyz_elems = (size_t)BB * NN * 3;
    const size_t feat_elems = (size_t)BB * CC * NN;

    if ((size_t)out_size == xyz_elems + feat_elems) {
        out_xyz = out;
        out_feat = out + xyz_elems;
    }

    cudaFuncSetAttribute(main_kernel,
                         cudaFuncAttributeMaxDynamicSharedMemorySize, MAIN_SMEM);
    cudaFuncSetAttribute(epilogue_kernel,
                         cudaFuncAttributeMaxDynamicSharedMemorySize, EPI_SMEM_BYTES);

    precompute_kernel<<<BN / 32, 256>>>(xyz, features, W_gu, W_gv,
                                        s_gu, b_gu, s_gv, b_gv, out_xyz);
    main_kernel<<<MAIN_GRID, 256, MAIN_SMEM>>>(idx, W_h, s_h, b_h);
    epilogue_kernel<<<BN / 128, 256, EPI_SMEM_BYTES>>>(W_f, s_f, b_f, features,
                                                       out_feat);
}

// round 15
// speedup vs baseline: 1.0856x; 1.0197x over previous
#include <cuda_runtime.h>
#include <cuda_fp16.h>
#include <cstdint>

// Problem constants
#define BB 4
#define NN 4096
#define KK 32
#define CC 64
#define FD 128
#define DHH 128
#define BN (BB * NN)
#define NT2 (BN / 2)           // M=64 tiles: 2 points per tile

// Scratch (no cudaMalloc allowed)
__device__ __half g_ctr_h[(size_t)BN * FD];   // h(ctr*s + b)
__device__ __half g_nbr_h[(size_t)BN * FD];   // h(v*s)
__device__ float  g_pooled[(size_t)BN * DHH];

// ---------------------------------------------------------------------------
// PTX helpers — baseline sm_80+ instructions only (compute_103-safe).
// ---------------------------------------------------------------------------
__device__ __forceinline__ uint32_t smem_u32(const void* p) {
    uint32_t a;
    asm("{ .reg .u64 t; cvta.to.shared.u64 t, %1; cvt.u32.u64 %0, t; }"
        : "=r"(a) : "l"(p));
    return a;
}

#define LDSM_X4(r0, r1, r2, r3, addr)                                        \
    asm volatile("ldmatrix.sync.aligned.m8n8.x4.shared.b16 {%0,%1,%2,%3}, [%4];" \
                 : "=r"(r0), "=r"(r1), "=r"(r2), "=r"(r3) : "r"(addr))

// fp16-accumulate MMA: D(2 packed regs) = A(4) * B(2) + D  — full-rate HMMA
#define MMA_F16_F16(d, a, b0, b1)                                            \
    asm volatile("mma.sync.aligned.m16n8k16.row.col.f16.f16.f16.f16 "        \
                 "{%0,%1}, {%2,%3,%4,%5}, {%6,%7}, {%0,%1};"                 \
                 : "+r"((d)[0]), "+r"((d)[1])                                \
                 : "r"((a)[0]), "r"((a)[1]), "r"((a)[2]), "r"((a)[3]),       \
                   "r"(b0), "r"(b1))

__device__ __forceinline__ uint32_t h2u(__half2 h) { return *(uint32_t*)&h; }

// ---------------------------------------------------------------------------
// Kernel 1: precompute pre-scaled fp16 tables (512 blocks, 32 pts each).
//   g_ctr_h[p][f] = h( (U1|Gv)[f]*s[f] + b[f] )
//   g_nbr_h[p][f] = h( (U2|Gv)[f]*s[f] )
// Restructured: compute Gv+U1+U2 in ONE phase (U2 in its own region), then
// ONE write phase emitting both tables -> 2 barriers instead of 6.
// Also performs the xyz passthrough copy (replaces separate memcpy).
// ---------------------------------------------------------------------------
#define WGV_S 68
__global__ void __launch_bounds__(256) precompute_kernel(
    const float* __restrict__ xyz, const float* __restrict__ features,
    const float* __restrict__ W_gu, const float* __restrict__ W_gv,
    const float* __restrict__ s_gu, const float* __restrict__ b_gu,
    const float* __restrict__ s_gv, const float* __restrict__ b_gv,
    float* __restrict__ out_xyz)
{
    __shared__ float sWgv[64 * WGV_S];
    __shared__ float sWgu[64 * 6];
    __shared__ float sF[64 * 33];
    __shared__ float sXyz[32 * 3];
    __shared__ float sOut[32 * 132];     // [np][0:64]=U1, [np][64:128]=Gv
    __shared__ float sU2[32 * 68];       // [np][0:64]=U2
    __shared__ float sS[128], sB[128];

    int t = threadIdx.x;
    int p0 = blockIdx.x * 32;
    int b = p0 >> 12;
    int n0 = p0 & (NN - 1);

    // xyz passthrough (independent of the rest)
    if (out_xyz) {
        for (int e = blockIdx.x * 256 + t; e < BB * NN * 3; e += gridDim.x * 256)
            out_xyz[e] = xyz[e];
    }

    for (int e = t; e < 64 * 64; e += 256)
        sWgv[(e & 63) * WGV_S + (e >> 6)] = W_gv[e];
    for (int e = t; e < 64 * 6; e += 256)
        sWgu[e] = W_gu[e];
    for (int e = t; e < 64 * 32; e += 256) {
        int c = e >> 5, np = e & 31;
        sF[c * 33 + np] = features[(size_t)b * CC * NN + (size_t)c * NN + n0 + np];
    }
    for (int e = t; e < 96; e += 256)
        sXyz[e] = xyz[(size_t)p0 * 3 + e];
    if (t < 64) { sS[t] = s_gu[t]; sB[t] = b_gu[t]; }
    else if (t < 128) { sS[t] = s_gv[t - 64]; sB[t] = b_gv[t - 64]; }
    __syncthreads();   // barrier 1: inputs staged

    // ---- compute phase: Gv + U1 + U2 (no intervening barriers) ----
    // Gv: thread (np = t&31, o0 = (t>>5)*8)
    {
        int np = t & 31;
        int o0 = (t >> 5) << 3;
        float acc[8];
#pragma unroll
        for (int j = 0; j < 8; j++) acc[j] = 0.f;
#pragma unroll 16
        for (int c = 0; c < 64; c++) {
            float a = sF[c * 33 + np];
            const float4* wp = (const float4*)&sWgv[c * WGV_S + o0];
            float4 w0 = wp[0], w1 = wp[1];
            acc[0] += a * w0.x; acc[1] += a * w0.y;
            acc[2] += a * w0.z; acc[3] += a * w0.w;
            acc[4] += a * w1.x; acc[5] += a * w1.y;
            acc[6] += a * w1.z; acc[7] += a * w1.w;
        }
#pragma unroll
        for (int j = 0; j < 8; j++)
            sOut[np * 132 + 64 + o0 + j] = acc[j];
    }
    // U1 and U2 (each thread: 8 (np,o) elements per loop)
    for (int e = t; e < 32 * 64; e += 256) {
        int np = e >> 6, o = e & 63;
        float x0 = sXyz[np * 3], x1 = sXyz[np * 3 + 1], x2 = sXyz[np * 3 + 2];
        const float* wg = &sWgu[o * 6];
        sOut[np * 132 + o] = wg[0] * x0 + wg[1] * x1 + wg[2] * x2;
        sU2[np * 68 + o]   = wg[3] * x0 + wg[4] * x1 + wg[5] * x2;
    }
    __syncthreads();   // barrier 2: all values computed

    // ---- single write phase: both tables, shared scale loads ----
    for (int e = t * 8; e < 32 * 128; e += 2048) {
        int np = e >> 7, f = e & 127;
        float4 s0 = *(const float4*)&sS[f], s1 = *(const float4*)&sS[f + 4];
        float4 c0 = *(const float4*)&sB[f], c1 = *(const float4*)&sB[f + 4];

        // ctr source: [U1 | Gv] in sOut
        const float* srcC = &sOut[np * 132 + f];
        float4 x0 = *(const float4*)srcC, x1 = *(const float4*)(srcC + 4);
        uint4 oc;
        oc.x = h2u(__float22half2_rn(make_float2(x0.x * s0.x + c0.x, x0.y * s0.y + c0.y)));
        oc.y = h2u(__float22half2_rn(make_float2(x0.z * s0.z + c0.z, x0.w * s0.w + c0.w)));
        oc.z = h2u(__float22half2_rn(make_float2(x1.x * s1.x + c1.x, x1.y * s1.y + c1.y)));
        oc.w = h2u(__float22half2_rn(make_float2(x1.z * s1.z + c1.z, x1.w * s1.w + c1.w)));
        *(uint4*)&g_ctr_h[(size_t)p0 * FD + e] = oc;

        // nbr source: f<64 -> U2, f>=64 -> Gv (segments are 8-aligned, 64|8)
        const float* srcN = (f < 64) ? &sU2[np * 68 + f] : srcC;
        float4 y0 = *(const float4*)srcN, y1 = *(const float4*)(srcN + 4);
        uint4 on;
        on.x = h2u(__float22half2_rn(make_float2(y0.x * s0.x, y0.y * s0.y)));
        on.y = h2u(__float22half2_rn(make_float2(y0.z * s0.z, y0.w * s0.w)));
        on.z = h2u(__float22half2_rn(make_float2(y1.x * s1.x, y1.y * s1.y)));
        on.w = h2u(__float22half2_rn(make_float2(y1.z * s1.z, y1.w * s1.w)));
        *(uint4*)&g_nbr_h[(size_t)p0 * FD + e] = on;
    }
}

// ---------------------------------------------------------------------------
// Kernel 2 (main): R14 winner, unchanged. fp16-accumulate HMMA.
// 256-thread CTAs, M=64 tiles (2 points), grid 304, 2 CTAs/SM.
// B fragments hoisted in registers, double-buffered A smem, one barrier/tile.
// ---------------------------------------------------------------------------
#define MAIN_GRID 304
#define RSB 272
#define RSW 68
#define S_WH 0                       // W_h fp16       34816
#define S_A0 34816                   // A buf 0        17408
#define S_A1 52224                   // A buf 1        17408
#define S_IDX 69632                  // 2x64 ints      512
#define S_SH  70144                  // s_h            512
#define S_BH  70656                  // b_h            512
#define MAIN_SMEM 71168

__global__ void __launch_bounds__(256, 2) main_kernel(
    const int* __restrict__ idx,
    const float* __restrict__ W_h,
    const float* __restrict__ s_h, const float* __restrict__ b_h)
{
    extern __shared__ __align__(16) char smem[];
    uint32_t sbase = smem_u32(smem);
    uint32_t* sWh = (uint32_t*)(smem + S_WH);
    int*   s_idx = (int*)(smem + S_IDX);
    float* s_sh = (float*)(smem + S_SH);
    float* s_bh = (float*)(smem + S_BH);

    int t = threadIdx.x;
    int lane = t & 31;
    int w = t >> 5;

    // gather mapping: feature quad fq (halves 4fq..4fq+3), row group rg (8 rows)
    int fq = t & 31;
    int rg = t >> 5;            // 0..7 -> rows rg*8 .. rg*8+7
    int ptg = rg >> 2;          // point of this row group (0/1)

    if (t < 128) { s_sh[t] = s_h[t]; s_bh[t] = b_h[t]; }

    // W_h -> fp16 padded [o][k]
    {
        int fp = t & 63, og = t >> 6;   // og 0..3, 32 rows each
#pragma unroll
        for (int ii = 0; ii < 32; ii++) {
            int o = og * 32 + ii;
            float2 wv = *(const float2*)&W_h[(size_t)o * 128 + 2 * fp];
            sWh[o * RSW + fp] = h2u(__float22half2_rn(make_float2(wv.x, wv.y)));
        }
    }

    const int grid = MAIN_GRID;
    int tile = blockIdx.x;

    // idx prologue: slot0 = tile, slot1 = tile+grid (64 ints per tile)
    if (t < 64) {
        int n = (tile * 2 + (t >> 5)) & (NN - 1);
        s_idx[t] = idx[n * KK + (t & 31)];
        int t1 = tile + grid;
        if (t1 < NT2) {
            int n1 = (t1 * 2 + (t >> 5)) & (NN - 1);
            s_idx[64 + t] = idx[n1 * KK + (t & 31)];
        }
    }
    __syncthreads();

    // mma mapping + hoisted B fragments (loop-invariant)
    int pt_m = w & 1;
    int nq = w >> 1;
    uint32_t a_base[2];
#pragma unroll
    for (int mt = 0; mt < 2; mt++) {
        int arow = pt_m * 32 + mt * 16 + (lane & 15);
        a_base[mt] = sbase + S_A0 + arow * RSB + ((lane >> 4) << 4);
    }
    uint32_t breg[8][2][4];
    {
        uint32_t b_base[2];
#pragma unroll
        for (int g = 0; g < 2; g++) {
            int brow = nq * 32 + g * 16 + (lane & 7) + ((lane >> 4) << 3);
            b_base[g] = sbase + S_WH + brow * RSB + (((lane >> 3) & 1) << 4);
        }
#pragma unroll
        for (int ks = 0; ks < 8; ks++)
#pragma unroll
            for (int g = 0; g < 2; g++)
                LDSM_X4(breg[ks][g][0], breg[ks][g][1], breg[ks][g][2], breg[ks][g][3],
                        b_base[g] + (uint32_t)ks * 32);
    }

    // prologue gather: tile0 (8 rows x 4 halves per thread, uint2)
    uint2 vreg[8];
    uint2 ctrq;
    {
        int p = tile * 2 + ptg;
        int b = p >> 12;
        ctrq = *(const uint2*)&g_ctr_h[(size_t)p * FD + 4 * fq];
        const __half* nbB = g_nbr_h + (size_t)b * NN * FD + 4 * fq;
        const int* si = s_idx + rg * 8;
#pragma unroll
        for (int qi = 0; qi < 8; qi++)
            vreg[qi] = *(const uint2*)&nbB[(size_t)si[qi] * FD];
    }

    int it = 0;
    for (; tile < NT2; tile += grid, it++) {
        uint32_t aoff = (it & 1) ? 17408u : 0u;
        uint32_t* sA = (uint32_t*)(smem + S_A0 + aoff);

        // ---- STS: fuse in fp16 (add + relu) ----
        {
            int rowb = rg * 8;
            __half2 z = __float2half2_rn(0.f);
            __half2 c0 = *(__half2*)&ctrq.x;
            __half2 c1 = *(__half2*)&ctrq.y;
#pragma unroll
            for (int qi = 0; qi < 8; qi++) {
                __half2 u0 = __hmax2(__hadd2(c0, *(__half2*)&vreg[qi].x), z);
                __half2 u1 = __hmax2(__hadd2(c1, *(__half2*)&vreg[qi].y), z);
                uint2 st; st.x = h2u(u0); st.y = h2u(u1);
                *(uint2*)&sA[(rowb + qi) * RSW + 2 * fq] = st;
            }
        }
        __syncthreads();   // the only barrier per tile

        // ---- idx prefetch tile+2*grid into slot (it&1) ----
        {
            int t2 = tile + 2 * grid;
            if (t < 64 && t2 < NT2) {
                int n = (t2 * 2 + (t >> 5)) & (NN - 1);
                s_idx[(it & 1) * 64 + t] = idx[n * KK + (t & 31)];
            }
        }
        // ---- gather tile+grid (hidden under MMA) ----
        int nt = tile + grid;
        uint2 ctr_next;
        if (nt < NT2) {
            int p = nt * 2 + ptg;
            int b = p >> 12;
            ctr_next = *(const uint2*)&g_ctr_h[(size_t)p * FD + 4 * fq];
            const __half* nbB = g_nbr_h + (size_t)b * NN * FD + 4 * fq;
            const int* si = s_idx + ((it + 1) & 1) * 64 + rg * 8;
#pragma unroll
            for (int qi = 0; qi < 8; qi++)
                vreg[qi] = *(const uint2*)&nbB[(size_t)si[qi] * FD];
        }

        // ---- MMA: A from smem (LDSM), B from registers, fp16 accumulate ----
        uint32_t accl[2][4][2];
#pragma unroll
        for (int mt = 0; mt < 2; mt++)
#pragma unroll
            for (int j = 0; j < 4; j++) {
                accl[mt][j][0] = 0u; accl[mt][j][1] = 0u;
            }

#pragma unroll
        for (int ks = 0; ks < 8; ks++) {
            uint32_t koff = (uint32_t)ks * 32 + aoff;
            uint32_t ah[2][4];
#pragma unroll
            for (int mt = 0; mt < 2; mt++)
                LDSM_X4(ah[mt][0], ah[mt][1], ah[mt][2], ah[mt][3], a_base[mt] + koff);
#pragma unroll
            for (int mt = 0; mt < 2; mt++)
#pragma unroll
                for (int g = 0; g < 2; g++) {
                    MMA_F16_F16(accl[mt][g * 2 + 0], ah[mt], breg[ks][g][0], breg[ks][g][1]);
                    MMA_F16_F16(accl[mt][g * 2 + 1], ah[mt], breg[ks][g][2], breg[ks][g][3]);
                }
        }

        // ---- pool: unpack fp16 acc, relu(d*sh+bh), mean over 32 rows ----
        {
            int p = tile * 2 + pt_m;
#pragma unroll
            for (int j = 0; j < 4; j++) {
                int col0 = nq * 32 + j * 8 + 2 * (lane & 3);
                float sc0 = s_sh[col0], sc1 = s_sh[col0 + 1];
                float bb0 = s_bh[col0], bb1 = s_bh[col0 + 1];
                float v0 = 0.f, v1 = 0.f;
#pragma unroll
                for (int mt = 0; mt < 2; mt++) {
                    float2 d0 = __half22float2(*(__half2*)&accl[mt][j][0]);
                    float2 d1 = __half22float2(*(__half2*)&accl[mt][j][1]);
                    v0 += fmaxf(d0.x * sc0 + bb0, 0.f) + fmaxf(d1.x * sc0 + bb0, 0.f);
                    v1 += fmaxf(d0.y * sc1 + bb1, 0.f) + fmaxf(d1.y * sc1 + bb1, 0.f);
                }
#pragma unroll
                for (int off = 4; off < 32; off <<= 1) {
                    v0 += __shfl_xor_sync(0xffffffffu, v0, off);
                    v1 += __shfl_xor_sync(0xffffffffu, v1, off);
                }
                if (lane < 4) {
                    *(float2*)&g_pooled[(size_t)p * DHH + nq * 32 + j * 8 + lane * 2] =
                        make_float2(v0 * (1.f / KK), v1 * (1.f / KK));
                }
            }
        }
        ctrq = ctr_next;
    }
}

// ---------------------------------------------------------------------------
// Kernel 3: final MLP epilogue. 128 points per block (W_f amortized 4x).
// ---------------------------------------------------------------------------
#define EPI_SWF (128 * 68)
#define EPI_SPOOL (32 * 129)
#define EPI_SOUT (64 * 33)
#define EPI_SMEM_BYTES ((EPI_SWF + EPI_SPOOL + EPI_SOUT) * 4)

__global__ void __launch_bounds__(256) epilogue_kernel(
    const float* __restrict__ W_f,
    const float* __restrict__ s_f, const float* __restrict__ b_f,
    const float* __restrict__ features,
    float* __restrict__ out)
{
    extern __shared__ float sm[];
    float* sWf = sm;
    float* sPool = sWf + EPI_SWF;
    float* sOutE = sPool + EPI_SPOOL;

    int t = threadIdx.x;

    for (int e = t; e < 64 * 128; e += 256) {
        int c = e >> 7, i = e & 127;
        sWf[i * 68 + c] = W_f[e];
    }

#pragma unroll 1
    for (int g = 0; g < 4; g++) {
        int p0 = blockIdx.x * 128 + g * 32;
        int b = p0 >> 12;
        int n0 = p0 & (NN - 1);

        __syncthreads();  // previous group's readers done / sWf ready
        for (int e = t; e < 32 * 128; e += 256) {
            int np = e >> 7, i = e & 127;
            sPool[np * 129 + i] = g_pooled[(size_t)p0 * DHH + e];
        }
        __syncthreads();

        {
            int np = t & 31;
            int c0 = (t >> 5) << 3;
            float acc[8];
#pragma unroll
            for (int j = 0; j < 8; j++) acc[j] = 0.f;
#pragma unroll 16
            for (int i = 0; i < 128; i++) {
                float a = sPool[np * 129 + i];
                const float4* wp = (const float4*)&sWf[i * 68 + c0];
                float4 w0 = wp[0], w1 = wp[1];
                acc[0] += a * w0.x; acc[1] += a * w0.y;
                acc[2] += a * w0.z; acc[3] += a * w0.w;
                acc[4] += a * w1.x; acc[5] += a * w1.y;
                acc[6] += a * w1.z; acc[7] += a * w1.w;
            }
#pragma unroll
            for (int j = 0; j < 8; j++) {
                int c = c0 + j;
                sOutE[c * 33 + np] = fmaxf(acc[j] * __ldg(&s_f[c]) + __ldg(&b_f[c]), 0.f);
            }
        }
        __syncthreads();

        for (int e = t; e < 64 * 32; e += 256) {
            int c = e >> 5, np = e & 31;
            size_t o = (size_t)b * CC * NN + (size_t)c * NN + n0 + np;
            out[o] = sOutE[c * 33 + np] + features[o];
        }
    }
}

// ---------------------------------------------------------------------------
extern "C" void kernel_launch(void* const* d_in, const int* in_sizes, int n_in,
                              void* d_out, int out_size)
{
    const float* xyz      = (const float*)d_in[0];
    const float* features = (const float*)d_in[1];
    const int*   idx      = (const int*)d_in[2];
    const float* W_gu     = (const float*)d_in[3];
    const float* s_gu     = (const float*)d_in[4];
    const float* b_gu     = (const float*)d_in[5];
    const float* W_gv     = (const float*)d_in[6];
    const float* s_gv     = (const float*)d_in[7];
    const float* b_gv     = (const float*)d_in[8];
    const float* W_h      = (const float*)d_in[9];
    const float* s_h      = (const float*)d_in[10];
    const float* b_h      = (const float*)d_in[11];
    const float* W_f      = (const float*)d_in[12];
    const float* s_f      = (const float*)d_in[13];
    const float* b_f      = (const float*)d_in[14];

    float* out = (float*)d_out;
    float* out_feat = out;
    float* out_xyz = nullptr;
    const size_t xyz_elems = (size_t)BB * NN * 3;
    const size_t feat_elems = (size_t)BB * CC * NN;

    if ((size_t)out_size == xyz_elems + feat_elems) {
        out_xyz = out;
        out_feat = out + xyz_elems;
    }

    cudaFuncSetAttribute(main_kernel,
                         cudaFuncAttributeMaxDynamicSharedMemorySize, MAIN_SMEM);
    cudaFuncSetAttribute(epilogue_kernel,
                         cudaFuncAttributeMaxDynamicSharedMemorySize, EPI_SMEM_BYTES);

    precompute_kernel<<<BN / 32, 256>>>(xyz, features, W_gu, W_gv,
                                        s_gu, b_gu, s_gv, b_gv, out_xyz);
    main_kernel<<<MAIN_GRID, 256, MAIN_SMEM>>>(idx, W_h, s_h, b_h);
    epilogue_kernel<<<BN / 128, 256, EPI_SMEM_BYTES>>>(W_f, s_f, b_f, features,
                                                       out_feat);
}